// round 2
// baseline (speedup 1.0000x reference)
#include <cuda_runtime.h>
#include <cstdint>

#define NN 64
#define C1 128
#define C2 256
#define H1 56
#define W1 56
#define H2 28
#define W2 28
#define HW2 (H2*W2)        // 784
#define NPIX (NN*HW2)      // 50176
#define TOT2 (NN*C2*HW2)   // 12845056

// ---------------- scratch (static device globals; no runtime allocation) ----------------
__device__ uint4 g_xb[NN*H1*W1];     // packed sign(x): [n][h][w], 128 ch -> 4 words
__device__ uint4 g_w1b[C2*9];        // packed sign(w1): [co][tap], 128 ch -> 4 words
__device__ uint4 g_w2b[C2*9*2];      // packed sign(w2): [co][tap][2], 256 ch -> 8 words
__device__ uint4 g_wsb[C2];          // packed sign(ws): [co], 128 ch -> 4 words
__device__ uint4 g_o1b[NPIX*2];      // packed sign(BN1 out): [n][oh][ow][2]
__device__ float g_t1[TOT2];         // conv1 raw output (pre-BN1)
__device__ float g_alpha[3];         // mean|w1|, mean|w2|, mean|ws|
__device__ float g_part[3*128];      // partial |w| sums
__device__ float g_mu[2*C2], g_rs[2*C2]; // BN1/BN2 per-channel mean & rsqrt(var+eps)

// ---------------- alpha = mean|w| (deterministic two-stage tree reduction) ----------------
__global__ void k_abs_partial(const float* __restrict__ w1, const float* __restrict__ w2,
                              const float* __restrict__ ws) {
    int t = blockIdx.y;
    const float* s = (t == 0) ? w1 : ((t == 1) ? w2 : ws);
    int n = (t == 0) ? C2*C1*9 : ((t == 1) ? C2*C2*9 : C2*C1);
    float acc = 0.f;
    for (int i = blockIdx.x*blockDim.x + threadIdx.x; i < n; i += gridDim.x*blockDim.x)
        acc += fabsf(s[i]);
    __shared__ float sh[256];
    sh[threadIdx.x] = acc; __syncthreads();
    for (int o = 128; o > 0; o >>= 1) {
        if (threadIdx.x < o) sh[threadIdx.x] += sh[threadIdx.x + o];
        __syncthreads();
    }
    if (threadIdx.x == 0) g_part[t*128 + blockIdx.x] = sh[0];
}

__global__ void k_abs_final() {
    __shared__ float sh[128];
    int tid = threadIdx.x;
    for (int t = 0; t < 3; t++) {
        sh[tid] = g_part[t*128 + tid]; __syncthreads();
        for (int o = 64; o > 0; o >>= 1) {
            if (tid < o) sh[tid] += sh[tid + o];
            __syncthreads();
        }
        if (tid == 0) {
            float n = (t == 0) ? (float)(C2*C1*9) : ((t == 1) ? (float)(C2*C2*9) : (float)(C2*C1));
            g_alpha[t] = sh[0] / n;
        }
        __syncthreads();
    }
}

// ---------------- pack weight sign bits ----------------
__global__ void k_pack_w(const float* __restrict__ w1, const float* __restrict__ w2,
                         const float* __restrict__ ws) {
    int idx = blockIdx.x*blockDim.x + threadIdx.x;
    if (idx < C2*9*4) {
        int co = idx/36, rem = idx%36, tap = rem/4, wd = rem%4;
        unsigned b = 0;
        for (int j = 0; j < 32; j++) {
            float v = w1[(co*C1 + wd*32 + j)*9 + tap];
            b |= (v >= 0.f ? 1u : 0u) << j;
        }
        ((unsigned*)g_w1b)[(co*9 + tap)*4 + wd] = b;
    } else if (idx < C2*9*4 + C2*9*8) {
        int k = idx - C2*9*4;
        int co = k/72, rem = k%72, tap = rem/8, wd = rem%8;
        unsigned b = 0;
        for (int j = 0; j < 32; j++) {
            float v = w2[(co*C2 + wd*32 + j)*9 + tap];
            b |= (v >= 0.f ? 1u : 0u) << j;
        }
        ((unsigned*)g_w2b)[(co*9 + tap)*8 + wd] = b;
    } else if (idx < C2*9*4 + C2*9*8 + C2*4) {
        int k = idx - (C2*9*4 + C2*9*8);
        int co = k/4, wd = k%4;
        unsigned b = 0;
        for (int j = 0; j < 32; j++) {
            float v = ws[co*C1 + wd*32 + j];
            b |= (v >= 0.f ? 1u : 0u) << j;
        }
        ((unsigned*)g_wsb)[co*4 + wd] = b;
    }
}

// ---------------- pack sign(x) along channels ----------------
__global__ void k_pack_x(const float* __restrict__ x) {
    int p = blockIdx.x*blockDim.x + threadIdx.x;
    if (p >= NN*H1*W1) return;
    int n = p / (H1*W1), hw = p - n*(H1*W1);
    unsigned wd[4];
    #pragma unroll
    for (int q = 0; q < 4; q++) {
        unsigned b = 0;
        for (int j = 0; j < 32; j++) {
            float v = x[(n*C1 + q*32 + j)*(H1*W1) + hw];
            b |= (v >= 0.f ? 1u : 0u) << j;
        }
        wd[q] = b;
    }
    g_xb[p] = make_uint4(wd[0], wd[1], wd[2], wd[3]);
}

// ---------------- conv1: 3x3 stride2 pad1, binarized, output = alpha1 * dot ----------------
__global__ void __launch_bounds__(224, 2) k_conv1() {
    int oh = blockIdx.x, n = blockIdx.y;
    __shared__ uint4 sin_[3*W1];
    for (int i = threadIdx.x; i < 3*W1; i += 224) {
        int r = i / W1, c = i - r*W1;
        int ih = 2*oh - 1 + r;
        if (ih >= 0) sin_[i] = g_xb[(n*H1 + ih)*W1 + c];
    }
    __syncthreads();
    int ow = threadIdx.x % 28;
    int cog = threadIdx.x / 28;
    uint4 xin[9]; unsigned vm[9]; int nval = 0;
    #pragma unroll
    for (int kh = 0; kh < 3; kh++)
        #pragma unroll
        for (int kw = 0; kw < 3; kw++) {
            int t = kh*3 + kw;
            int ih = 2*oh - 1 + kh, iw = 2*ow - 1 + kw;
            bool v = (ih >= 0) && (iw >= 0);      // upper bounds always valid (<=55)
            vm[t] = v ? 0xFFFFFFFFu : 0u; nval += v ? 1 : 0;
            int iwc = iw < 0 ? 0 : iw;
            xin[t] = sin_[kh*W1 + iwc];
        }
    float a1 = g_alpha[0];
    float base = 128.f * (float)nval;
    int obase = ((n*C2)*H2 + oh)*W2 + ow;
    for (int i = 0; i < 32; i++) {
        int co = cog*32 + i;
        const uint4* wp = &g_w1b[co*9];
        int p0 = 0, p1 = 0, p2 = 0, p3 = 0;
        #pragma unroll
        for (int t = 0; t < 9; t++) {
            uint4 w = wp[t]; unsigned m = vm[t];
            p0 += __popc((xin[t].x ^ w.x) & m);
            p1 += __popc((xin[t].y ^ w.y) & m);
            p2 += __popc((xin[t].z ^ w.z) & m);
            p3 += __popc((xin[t].w ^ w.w) & m);
        }
        int pop = (p0 + p1) + (p2 + p3);
        g_t1[obase + co*HW2] = a1 * (base - 2.f*(float)pop);
    }
}

// ---------------- per-channel BN stats (deterministic, double accum) ----------------
__global__ void k_stats(const float* __restrict__ src, int which) {
    const float* p = which ? src : g_t1;
    int co = blockIdx.x;
    double s = 0.0, s2 = 0.0;
    for (int i = threadIdx.x; i < NN*HW2; i += blockDim.x) {
        int n = i / HW2, r = i - n*HW2;
        float v = p[(n*C2 + co)*HW2 + r];
        s += (double)v; s2 += (double)v * (double)v;
    }
    __shared__ double sa[256], sb[256];
    sa[threadIdx.x] = s; sb[threadIdx.x] = s2; __syncthreads();
    for (int o = 128; o > 0; o >>= 1) {
        if (threadIdx.x < o) { sa[threadIdx.x] += sa[threadIdx.x+o]; sb[threadIdx.x] += sb[threadIdx.x+o]; }
        __syncthreads();
    }
    if (threadIdx.x == 0) {
        double m = sa[0] / (double)(NN*HW2);
        double var = sb[0] / (double)(NN*HW2) - m*m;
        g_mu[which*C2 + co] = (float)m;
        g_rs[which*C2 + co] = (float)(1.0 / sqrt(var + 1e-5));
    }
}

// ---------------- binarize BN1 output, pack 256 ch -> 8 words ----------------
__global__ void k_pack_o1(const float* __restrict__ g1, const float* __restrict__ b1) {
    int p = blockIdx.x*blockDim.x + threadIdx.x;
    if (p >= NPIX) return;
    int n = p / HW2, hw = p - n*HW2;
    unsigned wd[8];
    #pragma unroll
    for (int q = 0; q < 8; q++) {
        unsigned b = 0;
        for (int j = 0; j < 32; j++) {
            int c = q*32 + j;
            float t = g_t1[(n*C2 + c)*HW2 + hw];
            float o = (t - g_mu[c]) * g_rs[c] * g1[c] + b1[c];
            b |= (o >= 0.f ? 1u : 0u) << j;
        }
        wd[q] = b;
    }
    g_o1b[p*2]     = make_uint4(wd[0], wd[1], wd[2], wd[3]);
    g_o1b[p*2 + 1] = make_uint4(wd[4], wd[5], wd[6], wd[7]);
}

// ---------------- conv2 (3x3 s1 p1) + quantized 1x1 s2 shortcut, fused ----------------
__global__ void __launch_bounds__(224, 2) k_conv2(float* __restrict__ out) {
    int oh = blockIdx.x, n = blockIdx.y;
    __shared__ uint4 sin_[3*W2*2];
    for (int i = threadIdx.x; i < 3*W2*2; i += 224) {
        int r = i / (W2*2); int rem = i - r*(W2*2);   // rem = c*2 + half
        int ih = oh - 1 + r;
        if (ih >= 0 && ih < H2) sin_[i] = g_o1b[((n*H2 + ih)*W2)*2 + rem];
    }
    __syncthreads();
    int ow = threadIdx.x % 28, cog = threadIdx.x / 28;
    uint4 xa[9], xb2[9]; unsigned vm[9]; int nval = 0;
    #pragma unroll
    for (int kh = 0; kh < 3; kh++)
        #pragma unroll
        for (int kw = 0; kw < 3; kw++) {
            int t = kh*3 + kw;
            int ih = oh - 1 + kh, iw = ow - 1 + kw;
            bool v = ((unsigned)ih < H2) && ((unsigned)iw < W2);
            vm[t] = v ? 0xFFFFFFFFu : 0u; nval += v ? 1 : 0;
            int iwc = iw < 0 ? 0 : (iw > W2-1 ? W2-1 : iw);
            xa[t]  = sin_[(kh*W2 + iwc)*2];
            xb2[t] = sin_[(kh*W2 + iwc)*2 + 1];
        }
    uint4 xs = g_xb[(n*H1 + 2*oh)*W1 + 2*ow];    // shortcut input (always valid)
    float a2 = g_alpha[1], as_ = g_alpha[2];
    float base = 256.f * (float)nval;
    int obase = ((n*C2)*H2 + oh)*W2 + ow;
    for (int i = 0; i < 32; i++) {
        int co = cog*32 + i;
        const uint4* wp = &g_w2b[co*18];
        int p0 = 0, p1 = 0, p2 = 0, p3 = 0;
        #pragma unroll
        for (int t = 0; t < 9; t++) {
            uint4 wa = wp[2*t], wb = wp[2*t + 1]; unsigned m = vm[t];
            p0 += __popc((xa[t].x ^ wa.x) & m) + __popc((xb2[t].x ^ wb.x) & m);
            p1 += __popc((xa[t].y ^ wa.y) & m) + __popc((xb2[t].y ^ wb.y) & m);
            p2 += __popc((xa[t].z ^ wa.z) & m) + __popc((xb2[t].z ^ wb.z) & m);
            p3 += __popc((xa[t].w ^ wa.w) & m) + __popc((xb2[t].w ^ wb.w) & m);
        }
        int pop = (p0 + p1) + (p2 + p3);
        uint4 wv = g_wsb[co];
        int ps = __popc(xs.x ^ wv.x) + __popc(xs.y ^ wv.y)
               + __popc(xs.z ^ wv.z) + __popc(xs.w ^ wv.w);
        out[obase + co*HW2] = a2 * (base - 2.f*(float)pop) + as_ * (128.f - 2.f*(float)ps);
    }
}

// ---------------- final BN2 normalize (in-place on d_out) ----------------
__global__ void k_norm(float* __restrict__ out, const float* __restrict__ g2,
                       const float* __restrict__ b2) {
    int i = blockIdx.x*blockDim.x + threadIdx.x;
    if (i >= TOT2) return;
    int c = (i / HW2) & (C2 - 1);
    out[i] = (out[i] - g_mu[C2 + c]) * g_rs[C2 + c] * g2[c] + b2[c];
}

// ---------------- launch ----------------
extern "C" void kernel_launch(void* const* d_in, const int* in_sizes, int n_in,
                              void* d_out, int out_size) {
    const float* x  = (const float*)d_in[0];
    const float* w1 = (const float*)d_in[1];
    const float* g1 = (const float*)d_in[2];
    const float* b1 = (const float*)d_in[3];
    const float* w2 = (const float*)d_in[4];
    const float* g2 = (const float*)d_in[5];
    const float* b2 = (const float*)d_in[6];
    const float* ws = (const float*)d_in[7];
    float* out = (float*)d_out;

    k_abs_partial<<<dim3(128, 3), 256>>>(w1, w2, ws);
    k_abs_final<<<1, 128>>>();
    k_pack_w<<<112, 256>>>(w1, w2, ws);
    k_pack_x<<<(NN*H1*W1 + 255)/256, 256>>>(x);
    k_conv1<<<dim3(H2, NN), 224>>>();
    k_stats<<<C2, 256>>>(nullptr, 0);
    k_pack_o1<<<(NPIX + 127)/128, 128>>>(g1, b1);
    k_conv2<<<dim3(H2, NN), 224>>>(out);
    k_stats<<<C2, 256>>>(out, 1);
    k_norm<<<(TOT2 + 255)/256, 256>>>(out, g2, b2);
}

// round 3
// speedup vs baseline: 1.4147x; 1.4147x over previous
#include <cuda_runtime.h>
#include <cstdint>

#define NN 64
#define C1 128
#define C2 256
#define H1 56
#define W1 56
#define H2 28
#define W2 28
#define HW2 (H2*W2)        // 784
#define NPIX (NN*HW2)      // 50176
#define TOT2 (NN*C2*HW2)   // 12845056

// ---------------- scratch (static device globals; no runtime allocation) ----------------
__device__ uint4 g_xb[NN*H1*W1];     // packed sign(x): [n][h][w], 128 ch -> 4 words
__device__ uint4 g_w1b[C2*9];        // packed sign(w1): [co][tap], 128 ch -> 4 words
__device__ uint4 g_w2b[C2*9*2];      // packed sign(w2): [co][tap][2], 256 ch -> 8 words
__device__ uint4 g_wsb[C2];          // packed sign(ws): [co], 128 ch -> 4 words
__device__ uint4 g_o1b[NPIX*2];      // packed sign(BN1 out): [n][oh][ow][2]
__device__ short g_t1[TOT2];         // conv1 integer dot (pre-scale, pre-BN1)
__device__ float g_alpha[3];         // mean|w1|, mean|w2|, mean|ws|
__device__ float g_part[3*128];      // partial |w| sums
__device__ float g_mu[2*C2], g_rs[2*C2];
__device__ float g_A1[C2], g_B1[C2]; // BN1 binarize affine: sign(A1*I + B1)
__device__ float g_A2[C2], g_B2[C2]; // BN2 normalize affine: v*A2 + B2

// ---------------- alpha = mean|w| (deterministic two-stage tree reduction) ----------------
__global__ void k_abs_partial(const float* __restrict__ w1, const float* __restrict__ w2,
                              const float* __restrict__ ws) {
    int t = blockIdx.y;
    const float* s = (t == 0) ? w1 : ((t == 1) ? w2 : ws);
    int n = (t == 0) ? C2*C1*9 : ((t == 1) ? C2*C2*9 : C2*C1);
    float acc = 0.f;
    for (int i = blockIdx.x*blockDim.x + threadIdx.x; i < n; i += gridDim.x*blockDim.x)
        acc += fabsf(s[i]);
    __shared__ float sh[256];
    sh[threadIdx.x] = acc; __syncthreads();
    for (int o = 128; o > 0; o >>= 1) {
        if (threadIdx.x < o) sh[threadIdx.x] += sh[threadIdx.x + o];
        __syncthreads();
    }
    if (threadIdx.x == 0) g_part[t*128 + blockIdx.x] = sh[0];
}

__global__ void k_abs_final() {
    __shared__ float sh[128];
    int tid = threadIdx.x;
    for (int t = 0; t < 3; t++) {
        sh[tid] = g_part[t*128 + tid]; __syncthreads();
        for (int o = 64; o > 0; o >>= 1) {
            if (tid < o) sh[tid] += sh[tid + o];
            __syncthreads();
        }
        if (tid == 0) {
            float n = (t == 0) ? (float)(C2*C1*9) : ((t == 1) ? (float)(C2*C2*9) : (float)(C2*C1));
            g_alpha[t] = sh[0] / n;
        }
        __syncthreads();
    }
}

// ---------------- pack weight sign bits ----------------
__global__ void k_pack_w(const float* __restrict__ w1, const float* __restrict__ w2,
                         const float* __restrict__ ws) {
    int idx = blockIdx.x*blockDim.x + threadIdx.x;
    if (idx < C2*9*4) {
        int co = idx/36, rem = idx%36, tap = rem/4, wd = rem%4;
        unsigned b = 0;
        for (int j = 0; j < 32; j++) {
            float v = w1[(co*C1 + wd*32 + j)*9 + tap];
            b |= (v >= 0.f ? 1u : 0u) << j;
        }
        ((unsigned*)g_w1b)[(co*9 + tap)*4 + wd] = b;
    } else if (idx < C2*9*4 + C2*9*8) {
        int k = idx - C2*9*4;
        int co = k/72, rem = k%72, tap = rem/8, wd = rem%8;
        unsigned b = 0;
        for (int j = 0; j < 32; j++) {
            float v = w2[(co*C2 + wd*32 + j)*9 + tap];
            b |= (v >= 0.f ? 1u : 0u) << j;
        }
        ((unsigned*)g_w2b)[(co*9 + tap)*8 + wd] = b;
    } else if (idx < C2*9*4 + C2*9*8 + C2*4) {
        int k = idx - (C2*9*4 + C2*9*8);
        int co = k/4, wd = k%4;
        unsigned b = 0;
        for (int j = 0; j < 32; j++) {
            float v = ws[co*C1 + wd*32 + j];
            b |= (v >= 0.f ? 1u : 0u) << j;
        }
        ((unsigned*)g_wsb)[co*4 + wd] = b;
    }
}

// ---------------- pack sign(x) along channels (integer sign-bit extraction) ----------------
__global__ void k_pack_x(const float* __restrict__ x) {
    int p = blockIdx.x*blockDim.x + threadIdx.x;
    if (p >= NN*H1*W1) return;
    int n = p / (H1*W1), hw = p - n*(H1*W1);
    const unsigned* xu = (const unsigned*)x;
    unsigned wd[4];
    #pragma unroll
    for (int q = 0; q < 4; q++) {
        unsigned b = 0;
        #pragma unroll 8
        for (int j = 0; j < 32; j++) {
            unsigned u = xu[(n*C1 + q*32 + j)*(H1*W1) + hw];
            b |= ((~u) >> 31) << j;    // 1 iff sign bit clear (v >= 0)
        }
        wd[q] = b;
    }
    g_xb[p] = make_uint4(wd[0], wd[1], wd[2], wd[3]);
}

// ---------------- conv1: 3x3 stride2 pad1, binarized; writes INTEGER dot (int16) ----------------
__global__ void __launch_bounds__(224, 2) k_conv1() {
    int oh = blockIdx.x, n = blockIdx.y;
    __shared__ uint4 sin_[3*W1];
    for (int i = threadIdx.x; i < 3*W1; i += 224) {
        int r = i / W1, c = i - r*W1;
        int ih = 2*oh - 1 + r;
        if (ih >= 0) sin_[i] = g_xb[(n*H1 + ih)*W1 + c];
    }
    __syncthreads();
    int ow = threadIdx.x % 28;
    int cog = threadIdx.x / 28;
    uint4 xin[9]; unsigned vm[9]; int nval = 0;
    #pragma unroll
    for (int kh = 0; kh < 3; kh++)
        #pragma unroll
        for (int kw = 0; kw < 3; kw++) {
            int t = kh*3 + kw;
            int ih = 2*oh - 1 + kh, iw = 2*ow - 1 + kw;
            bool v = (ih >= 0) && (iw >= 0);
            vm[t] = v ? 0xFFFFFFFFu : 0u; nval += v ? 1 : 0;
            int iwc = iw < 0 ? 0 : iw;
            xin[t] = sin_[kh*W1 + iwc];
        }
    int base = 128 * nval;
    int obase = ((n*C2)*H2 + oh)*W2 + ow;
    for (int i = 0; i < 32; i++) {
        int co = cog*32 + i;
        const uint4* wp = &g_w1b[co*9];
        int p0 = 0, p1 = 0, p2 = 0, p3 = 0;
        #pragma unroll
        for (int t = 0; t < 9; t++) {
            uint4 w = wp[t]; unsigned m = vm[t];
            p0 += __popc((xin[t].x ^ w.x) & m);
            p1 += __popc((xin[t].y ^ w.y) & m);
            p2 += __popc((xin[t].z ^ w.z) & m);
            p3 += __popc((xin[t].w ^ w.w) & m);
        }
        int pop = (p0 + p1) + (p2 + p3);
        g_t1[obase + co*HW2] = (short)(base - 2*pop);
    }
}

// ---------------- BN1 stats: exact integer accumulation over int16 dots ----------------
__global__ void __launch_bounds__(512) k_stats1(const float* __restrict__ g1,
                                                const float* __restrict__ b1) {
    int co = blockIdx.x;
    int s = 0; long long s2 = 0;
    for (int j = threadIdx.x; j < NPIX/2; j += 512) {
        int i = 2*j;
        int n = i / HW2, r = i - n*HW2;
        unsigned u = *(const unsigned*)&g_t1[(n*C2 + co)*HW2 + r];
        int v0 = (int)(short)(u & 0xFFFFu);
        int v1 = (int)(short)(u >> 16);
        s += v0 + v1;
        s2 += (long long)(v0*v0 + v1*v1);
    }
    __shared__ int sa[512]; __shared__ long long sb[512];
    sa[threadIdx.x] = s; sb[threadIdx.x] = s2; __syncthreads();
    for (int o = 256; o > 0; o >>= 1) {
        if (threadIdx.x < o) { sa[threadIdx.x] += sa[threadIdx.x+o]; sb[threadIdx.x] += sb[threadIdx.x+o]; }
        __syncthreads();
    }
    if (threadIdx.x == 0) {
        double a1 = (double)g_alpha[0];
        double mi  = (double)sa[0] / (double)NPIX;
        double vi  = (double)sb[0] / (double)NPIX - mi*mi;
        double mu  = a1 * mi;
        double var = a1*a1 * vi;
        float rs = (float)(1.0 / sqrt(var + 1e-5));
        float mus = (float)mu;
        g_mu[co] = mus; g_rs[co] = rs;
        float gc = g1[co];
        g_A1[co] = (float)(a1) * rs * gc;
        g_B1[co] = b1[co] - mus * rs * gc;
    }
}

// ---------------- binarize BN1 output (one FMA + sign per element), pack 256 ch ----------------
__global__ void k_pack_o1() {
    __shared__ float shA[C2], shB[C2];
    for (int i = threadIdx.x; i < C2; i += blockDim.x) { shA[i] = g_A1[i]; shB[i] = g_B1[i]; }
    __syncthreads();
    int p = blockIdx.x*blockDim.x + threadIdx.x;
    if (p >= NPIX) return;
    int n = p / HW2, hw = p - n*HW2;
    unsigned wd[8];
    #pragma unroll
    for (int q = 0; q < 8; q++) {
        unsigned b = 0;
        #pragma unroll 8
        for (int j = 0; j < 32; j++) {
            int c = q*32 + j;
            float o = fmaf(shA[c], (float)(int)g_t1[(n*C2 + c)*HW2 + hw], shB[c]);
            b |= (o >= 0.f ? 1u : 0u) << j;
        }
        wd[q] = b;
    }
    g_o1b[p*2]     = make_uint4(wd[0], wd[1], wd[2], wd[3]);
    g_o1b[p*2 + 1] = make_uint4(wd[4], wd[5], wd[6], wd[7]);
}

// ---------------- conv2 (3x3 s1 p1) + quantized 1x1 s2 shortcut, fused ----------------
__global__ void __launch_bounds__(224, 2) k_conv2(float* __restrict__ out) {
    int oh = blockIdx.x, n = blockIdx.y;
    __shared__ uint4 sin_[3*W2*2];
    for (int i = threadIdx.x; i < 3*W2*2; i += 224) {
        int r = i / (W2*2); int rem = i - r*(W2*2);
        int ih = oh - 1 + r;
        if (ih >= 0 && ih < H2) sin_[i] = g_o1b[((n*H2 + ih)*W2)*2 + rem];
    }
    __syncthreads();
    int ow = threadIdx.x % 28, cog = threadIdx.x / 28;
    uint4 xa[9], xb2[9]; unsigned vm[9]; int nval = 0;
    #pragma unroll
    for (int kh = 0; kh < 3; kh++)
        #pragma unroll
        for (int kw = 0; kw < 3; kw++) {
            int t = kh*3 + kw;
            int ih = oh - 1 + kh, iw = ow - 1 + kw;
            bool v = ((unsigned)ih < H2) && ((unsigned)iw < W2);
            vm[t] = v ? 0xFFFFFFFFu : 0u; nval += v ? 1 : 0;
            int iwc = iw < 0 ? 0 : (iw > W2-1 ? W2-1 : iw);
            xa[t]  = sin_[(kh*W2 + iwc)*2];
            xb2[t] = sin_[(kh*W2 + iwc)*2 + 1];
        }
    uint4 xs = g_xb[(n*H1 + 2*oh)*W1 + 2*ow];
    float a2 = g_alpha[1], as_ = g_alpha[2];
    float base = 256.f * (float)nval;
    int obase = ((n*C2)*H2 + oh)*W2 + ow;
    for (int i = 0; i < 32; i++) {
        int co = cog*32 + i;
        const uint4* wp = &g_w2b[co*18];
        int p0 = 0, p1 = 0, p2 = 0, p3 = 0;
        #pragma unroll
        for (int t = 0; t < 9; t++) {
            uint4 wa = wp[2*t], wb = wp[2*t + 1]; unsigned m = vm[t];
            p0 += __popc((xa[t].x ^ wa.x) & m) + __popc((xb2[t].x ^ wb.x) & m);
            p1 += __popc((xa[t].y ^ wa.y) & m) + __popc((xb2[t].y ^ wb.y) & m);
            p2 += __popc((xa[t].z ^ wa.z) & m) + __popc((xb2[t].z ^ wb.z) & m);
            p3 += __popc((xa[t].w ^ wa.w) & m) + __popc((xb2[t].w ^ wb.w) & m);
        }
        int pop = (p0 + p1) + (p2 + p3);
        uint4 wv = g_wsb[co];
        int ps = __popc(xs.x ^ wv.x) + __popc(xs.y ^ wv.y)
               + __popc(xs.z ^ wv.z) + __popc(xs.w ^ wv.w);
        out[obase + co*HW2] = fmaf(a2, base - 2.f*(float)pop, as_ * (128.f - 2.f*(float)ps));
    }
}

// ---------------- BN2 stats: f32 per-thread, double block tree (no fp64 hot path) ----------------
__global__ void __launch_bounds__(512) k_stats2(const float* __restrict__ out,
                                                const float* __restrict__ g2,
                                                const float* __restrict__ b2) {
    int co = blockIdx.x;
    float s = 0.f, s2 = 0.f;
    for (int i = threadIdx.x; i < NPIX; i += 512) {
        int n = i / HW2, r = i - n*HW2;
        float v = out[(n*C2 + co)*HW2 + r];
        s += v; s2 = fmaf(v, v, s2);
    }
    __shared__ double sa[512], sb[512];
    sa[threadIdx.x] = (double)s; sb[threadIdx.x] = (double)s2; __syncthreads();
    for (int o = 256; o > 0; o >>= 1) {
        if (threadIdx.x < o) { sa[threadIdx.x] += sa[threadIdx.x+o]; sb[threadIdx.x] += sb[threadIdx.x+o]; }
        __syncthreads();
    }
    if (threadIdx.x == 0) {
        double m = sa[0] / (double)NPIX;
        double var = sb[0] / (double)NPIX - m*m;
        float rs = (float)(1.0 / sqrt(var + 1e-5));
        float mus = (float)m;
        g_mu[C2 + co] = mus; g_rs[C2 + co] = rs;
        float gc = g2[co];
        g_A2[co] = rs * gc;
        g_B2[co] = b2[co] - mus * rs * gc;
    }
}

// ---------------- final BN2 normalize (in-place on d_out, one FMA) ----------------
__global__ void k_norm(float* __restrict__ out) {
    int i = blockIdx.x*blockDim.x + threadIdx.x;
    if (i >= TOT2) return;
    int c = (i / HW2) & (C2 - 1);
    out[i] = fmaf(out[i], g_A2[c], g_B2[c]);
}

// ---------------- launch ----------------
extern "C" void kernel_launch(void* const* d_in, const int* in_sizes, int n_in,
                              void* d_out, int out_size) {
    const float* x  = (const float*)d_in[0];
    const float* w1 = (const float*)d_in[1];
    const float* g1 = (const float*)d_in[2];
    const float* b1 = (const float*)d_in[3];
    const float* w2 = (const float*)d_in[4];
    const float* g2 = (const float*)d_in[5];
    const float* b2 = (const float*)d_in[6];
    const float* ws = (const float*)d_in[7];
    float* out = (float*)d_out;

    k_abs_partial<<<dim3(128, 3), 256>>>(w1, w2, ws);
    k_abs_final<<<1, 128>>>();
    k_pack_w<<<112, 256>>>(w1, w2, ws);
    k_pack_x<<<(NN*H1*W1 + 255)/256, 256>>>(x);
    k_conv1<<<dim3(H2, NN), 224>>>();
    k_stats1<<<C2, 512>>>(g1, b1);
    k_pack_o1<<<(NPIX + 127)/128, 128>>>();
    k_conv2<<<dim3(H2, NN), 224>>>(out);
    k_stats2<<<C2, 512>>>(out, g2, b2);
    k_norm<<<(TOT2 + 255)/256, 256>>>(out);
}

// round 4
// speedup vs baseline: 1.4210x; 1.0045x over previous
#include <cuda_runtime.h>
#include <cstdint>

#define NN 64
#define C1 128
#define C2 256
#define H1 56
#define W1 56
#define H2 28
#define W2 28
#define HW1 (H1*W1)        // 3136
#define HW2 (H2*W2)        // 784
#define NPIX (NN*HW2)      // 50176
#define TOT2 (NN*C2*HW2)   // 12845056

// ---------------- scratch (static device globals; no runtime allocation) ----------------
__device__ uint4 g_xb[NN*H1*W1];     // packed sign(x): [n][h][w], 128 ch -> 4 words
__device__ uint4 g_w1b[C2*9];        // packed sign(w1): [co][tap], 128 ch -> 4 words
__device__ uint4 g_w2b[C2*9*2];      // packed sign(w2): [co][tap][2], 256 ch -> 8 words
__device__ uint4 g_wsb[C2];          // packed sign(ws): [co], 128 ch -> 4 words
__device__ uint4 g_o1b[NPIX*2];      // packed sign(BN1 out): [n][oh][ow][2]
__device__ short g_t1[TOT2];         // conv1 integer dot (pre-scale, pre-BN1)
__device__ float g_alpha[3];         // mean|w1|, mean|w2|, mean|ws|
__device__ float g_part[3*128];      // partial |w| sums
__device__ float g_mu[2*C2], g_rs[2*C2];
__device__ float g_A1[C2], g_B1[C2]; // BN1 binarize affine: sign(A1*I + B1)
__device__ float g_A2[C2], g_B2[C2]; // BN2 normalize affine: v*A2 + B2

// ---------------- alpha = mean|w| (deterministic two-stage tree reduction) ----------------
__global__ void k_abs_partial(const float* __restrict__ w1, const float* __restrict__ w2,
                              const float* __restrict__ ws) {
    int t = blockIdx.y;
    const float* s = (t == 0) ? w1 : ((t == 1) ? w2 : ws);
    int n = (t == 0) ? C2*C1*9 : ((t == 1) ? C2*C2*9 : C2*C1);
    float acc = 0.f;
    for (int i = blockIdx.x*blockDim.x + threadIdx.x; i < n; i += gridDim.x*blockDim.x)
        acc += fabsf(s[i]);
    __shared__ float sh[256];
    sh[threadIdx.x] = acc; __syncthreads();
    for (int o = 128; o > 0; o >>= 1) {
        if (threadIdx.x < o) sh[threadIdx.x] += sh[threadIdx.x + o];
        __syncthreads();
    }
    if (threadIdx.x == 0) g_part[t*128 + blockIdx.x] = sh[0];
}

__global__ void k_abs_final() {
    __shared__ float sh[128];
    int tid = threadIdx.x;
    for (int t = 0; t < 3; t++) {
        sh[tid] = g_part[t*128 + tid]; __syncthreads();
        for (int o = 64; o > 0; o >>= 1) {
            if (tid < o) sh[tid] += sh[tid + o];
            __syncthreads();
        }
        if (tid == 0) {
            float n = (t == 0) ? (float)(C2*C1*9) : ((t == 1) ? (float)(C2*C2*9) : (float)(C2*C1));
            g_alpha[t] = sh[0] / n;
        }
        __syncthreads();
    }
}

// ---------------- pack weight sign bits ----------------
__global__ void k_pack_w(const float* __restrict__ w1, const float* __restrict__ w2,
                         const float* __restrict__ ws) {
    int idx = blockIdx.x*blockDim.x + threadIdx.x;
    if (idx < C2*9*4) {
        int co = idx/36, rem = idx%36, tap = rem/4, wd = rem%4;
        unsigned b = 0;
        for (int j = 0; j < 32; j++) {
            float v = w1[(co*C1 + wd*32 + j)*9 + tap];
            b |= (v >= 0.f ? 1u : 0u) << j;
        }
        ((unsigned*)g_w1b)[(co*9 + tap)*4 + wd] = b;
    } else if (idx < C2*9*4 + C2*9*8) {
        int k = idx - C2*9*4;
        int co = k/72, rem = k%72, tap = rem/8, wd = rem%8;
        unsigned b = 0;
        for (int j = 0; j < 32; j++) {
            float v = w2[(co*C2 + wd*32 + j)*9 + tap];
            b |= (v >= 0.f ? 1u : 0u) << j;
        }
        ((unsigned*)g_w2b)[(co*9 + tap)*8 + wd] = b;
    } else if (idx < C2*9*4 + C2*9*8 + C2*4) {
        int k = idx - (C2*9*4 + C2*9*8);
        int co = k/4, wd = k%4;
        unsigned b = 0;
        for (int j = 0; j < 32; j++) {
            float v = ws[co*C1 + wd*32 + j];
            b |= (v >= 0.f ? 1u : 0u) << j;
        }
        ((unsigned*)g_wsb)[co*4 + wd] = b;
    }
}

// ---------------- pack sign(x): 4 pixels/thread, float4 loads ----------------
__global__ void k_pack_x(const float* __restrict__ x) {
    int p4 = blockIdx.x*blockDim.x + threadIdx.x;
    if (p4 >= NN*HW1/4) return;
    int n = p4 / (HW1/4), hw4 = (p4 - n*(HW1/4)) * 4;
    const float4* xv = (const float4*)x;
    unsigned wd[4][4];
    #pragma unroll
    for (int q = 0; q < 4; q++) {
        unsigned b0 = 0, b1 = 0, b2 = 0, b3 = 0;
        #pragma unroll 8
        for (int j = 0; j < 32; j++) {
            float4 v = xv[((n*C1 + q*32 + j)*HW1 + hw4) >> 2];
            b0 |= (v.x >= 0.f ? 1u : 0u) << j;
            b1 |= (v.y >= 0.f ? 1u : 0u) << j;
            b2 |= (v.z >= 0.f ? 1u : 0u) << j;
            b3 |= (v.w >= 0.f ? 1u : 0u) << j;
        }
        wd[0][q] = b0; wd[1][q] = b1; wd[2][q] = b2; wd[3][q] = b3;
    }
    #pragma unroll
    for (int k = 0; k < 4; k++)
        g_xb[n*HW1 + hw4 + k] = make_uint4(wd[k][0], wd[k][1], wd[k][2], wd[k][3]);
}

// ---------------- conv1: 3x3 stride2 pad1, weights staged in smem ----------------
__global__ void __launch_bounds__(224, 2) k_conv1() {
    int oh = blockIdx.x, n = blockIdx.y;
    __shared__ uint4 sin_[3*W1];        // 2688 B
    __shared__ uint4 sw[C2*9];          // 36864 B
    for (int i = threadIdx.x; i < 3*W1; i += 224) {
        int r = i / W1, c = i - r*W1;
        int ih = 2*oh - 1 + r;
        if (ih >= 0) sin_[i] = g_xb[(n*H1 + ih)*W1 + c];
    }
    for (int i = threadIdx.x; i < C2*9; i += 224) sw[i] = g_w1b[i];
    __syncthreads();
    int ow = threadIdx.x % 28;
    int cog = threadIdx.x / 28;
    uint4 xin[9]; unsigned vm[9]; int nval = 0;
    #pragma unroll
    for (int kh = 0; kh < 3; kh++)
        #pragma unroll
        for (int kw = 0; kw < 3; kw++) {
            int t = kh*3 + kw;
            int ih = 2*oh - 1 + kh, iw = 2*ow - 1 + kw;
            bool v = (ih >= 0) && (iw >= 0);
            vm[t] = v ? 0xFFFFFFFFu : 0u; nval += v ? 1 : 0;
            int iwc = iw < 0 ? 0 : iw;
            xin[t] = sin_[kh*W1 + iwc];
        }
    int base = 128 * nval;
    int obase = ((n*C2)*H2 + oh)*W2 + ow;
    for (int i = 0; i < 32; i++) {
        int co = cog*32 + i;
        const uint4* wp = &sw[co*9];
        int p0 = 0, p1 = 0, p2 = 0, p3 = 0;
        #pragma unroll
        for (int t = 0; t < 9; t++) {
            uint4 w = wp[t]; unsigned m = vm[t];
            p0 += __popc((xin[t].x ^ w.x) & m);
            p1 += __popc((xin[t].y ^ w.y) & m);
            p2 += __popc((xin[t].z ^ w.z) & m);
            p3 += __popc((xin[t].w ^ w.w) & m);
        }
        int pop = (p0 + p1) + (p2 + p3);
        g_t1[obase + co*HW2] = (short)(base - 2*pop);
    }
}

// ---------------- BN1 stats: exact integer accumulation over int16 dots ----------------
__global__ void __launch_bounds__(512) k_stats1(const float* __restrict__ g1,
                                                const float* __restrict__ b1) {
    int co = blockIdx.x;
    int s = 0; long long s2 = 0;
    for (int j = threadIdx.x; j < NPIX/2; j += 512) {
        int i = 2*j;
        int n = i / HW2, r = i - n*HW2;
        unsigned u = *(const unsigned*)&g_t1[(n*C2 + co)*HW2 + r];
        int v0 = (int)(short)(u & 0xFFFFu);
        int v1 = (int)(short)(u >> 16);
        s += v0 + v1;
        s2 += (long long)(v0*v0 + v1*v1);
    }
    __shared__ int sa[512]; __shared__ long long sb[512];
    sa[threadIdx.x] = s; sb[threadIdx.x] = s2; __syncthreads();
    for (int o = 256; o > 0; o >>= 1) {
        if (threadIdx.x < o) { sa[threadIdx.x] += sa[threadIdx.x+o]; sb[threadIdx.x] += sb[threadIdx.x+o]; }
        __syncthreads();
    }
    if (threadIdx.x == 0) {
        double a1 = (double)g_alpha[0];
        double mi  = (double)sa[0] / (double)NPIX;
        double vi  = (double)sb[0] / (double)NPIX - mi*mi;
        double mu  = a1 * mi;
        double var = a1*a1 * vi;
        float rs = (float)(1.0 / sqrt(var + 1e-5));
        float mus = (float)mu;
        g_mu[co] = mus; g_rs[co] = rs;
        float gc = g1[co];
        g_A1[co] = (float)(a1) * rs * gc;
        g_B1[co] = b1[co] - mus * rs * gc;
    }
}

// ---------------- binarize+pack BN1 output: smem transpose + ballot ----------------
// grid: (25, NN); tile t covers pixels [t*32, t*32+P) of image n (last tile P=16)
__global__ void __launch_bounds__(256) k_pack_o1() {
    __shared__ int   sarr[C2*33];       // padded: stride 33 -> conflict-free column reads
    __shared__ float shA[C2], shB[C2];
    int tid = threadIdx.x, wq = tid >> 5, lane = tid & 31;
    int tidx = blockIdx.x, n = blockIdx.y;
    int hw0 = tidx * 32;
    int P = (hw0 + 32 <= HW2) ? 32 : (HW2 - hw0);
    if (tid < C2) { shA[tid] = g_A1[tid]; shB[tid] = g_B1[tid]; }
    // phase 1: coalesced load, transpose into smem
    for (int c = wq; c < C2; c += 8) {
        if (lane < P)
            sarr[c*33 + lane] = (int)g_t1[(n*C2 + c)*HW2 + hw0 + lane];
    }
    __syncthreads();
    // phase 2: warp wq handles channel group wq (channels wq*32 + lane)
    int ch = wq*32 + lane;
    float A = shA[ch], B = shB[ch];
    unsigned myword = 0;
    for (int px = 0; px < P; px++) {
        float o = fmaf(A, (float)sarr[ch*33 + px], B);
        unsigned w = __ballot_sync(0xFFFFFFFFu, o >= 0.f);
        if (lane == px) myword = w;
    }
    if (lane < P)
        ((unsigned*)g_o1b)[(n*HW2 + hw0 + lane)*8 + wq] = myword;
}

// ---------------- conv2 (3x3 s1 p1) + 1x1 shortcut; co split over blockIdx.z ----------------
__global__ void __launch_bounds__(224, 2) k_conv2(float* __restrict__ out) {
    int oh = blockIdx.x, n = blockIdx.y, coh = blockIdx.z;
    __shared__ uint4 sin_[3*W2*2];      // 2688 B
    __shared__ uint4 sw[128*18];        // 36864 B
    __shared__ uint4 sws[128];          // 2048 B
    for (int i = threadIdx.x; i < 3*W2*2; i += 224) {
        int r = i / (W2*2); int rem = i - r*(W2*2);
        int ih = oh - 1 + r;
        if (ih >= 0 && ih < H2) sin_[i] = g_o1b[((n*H2 + ih)*W2)*2 + rem];
    }
    for (int i = threadIdx.x; i < 128*18; i += 224) sw[i] = g_w2b[coh*128*18 + i];
    if (threadIdx.x < 128) sws[threadIdx.x] = g_wsb[coh*128 + threadIdx.x];
    __syncthreads();
    int ow = threadIdx.x % 28, cog = threadIdx.x / 28;
    uint4 xa[9], xb2[9]; unsigned vm[9]; int nval = 0;
    #pragma unroll
    for (int kh = 0; kh < 3; kh++)
        #pragma unroll
        for (int kw = 0; kw < 3; kw++) {
            int t = kh*3 + kw;
            int ih = oh - 1 + kh, iw = ow - 1 + kw;
            bool v = ((unsigned)ih < H2) && ((unsigned)iw < W2);
            vm[t] = v ? 0xFFFFFFFFu : 0u; nval += v ? 1 : 0;
            int iwc = iw < 0 ? 0 : (iw > W2-1 ? W2-1 : iw);
            xa[t]  = sin_[(kh*W2 + iwc)*2];
            xb2[t] = sin_[(kh*W2 + iwc)*2 + 1];
        }
    uint4 xs = g_xb[(n*H1 + 2*oh)*W1 + 2*ow];
    float a2 = g_alpha[1], as_ = g_alpha[2];
    float base = 256.f * (float)nval;
    int obase = ((n*C2 + coh*128)*H2 + oh)*W2 + ow;
    for (int i = 0; i < 16; i++) {
        int col = cog*16 + i;              // local channel 0..127
        const uint4* wp = &sw[col*18];
        int p0 = 0, p1 = 0, p2 = 0, p3 = 0;
        #pragma unroll
        for (int t = 0; t < 9; t++) {
            uint4 wa = wp[2*t], wb = wp[2*t + 1]; unsigned m = vm[t];
            p0 += __popc((xa[t].x ^ wa.x) & m) + __popc((xb2[t].x ^ wb.x) & m);
            p1 += __popc((xa[t].y ^ wa.y) & m) + __popc((xb2[t].y ^ wb.y) & m);
            p2 += __popc((xa[t].z ^ wa.z) & m) + __popc((xb2[t].z ^ wb.z) & m);
            p3 += __popc((xa[t].w ^ wa.w) & m) + __popc((xb2[t].w ^ wb.w) & m);
        }
        int pop = (p0 + p1) + (p2 + p3);
        uint4 wv = sws[col];
        int ps = __popc(xs.x ^ wv.x) + __popc(xs.y ^ wv.y)
               + __popc(xs.z ^ wv.z) + __popc(xs.w ^ wv.w);
        out[obase + col*HW2] = fmaf(a2, base - 2.f*(float)pop, as_ * (128.f - 2.f*(float)ps));
    }
}

// ---------------- BN2 stats: f32 per-thread, double block tree ----------------
__global__ void __launch_bounds__(512) k_stats2(const float* __restrict__ out,
                                                const float* __restrict__ g2,
                                                const float* __restrict__ b2) {
    int co = blockIdx.x;
    float s = 0.f, s2 = 0.f;
    for (int i = threadIdx.x; i < NPIX; i += 512) {
        int n = i / HW2, r = i - n*HW2;
        float v = out[(n*C2 + co)*HW2 + r];
        s += v; s2 = fmaf(v, v, s2);
    }
    __shared__ double sa[512], sb[512];
    sa[threadIdx.x] = (double)s; sb[threadIdx.x] = (double)s2; __syncthreads();
    for (int o = 256; o > 0; o >>= 1) {
        if (threadIdx.x < o) { sa[threadIdx.x] += sa[threadIdx.x+o]; sb[threadIdx.x] += sb[threadIdx.x+o]; }
        __syncthreads();
    }
    if (threadIdx.x == 0) {
        double m = sa[0] / (double)NPIX;
        double var = sb[0] / (double)NPIX - m*m;
        float rs = (float)(1.0 / sqrt(var + 1e-5));
        float mus = (float)m;
        g_mu[C2 + co] = mus; g_rs[C2 + co] = rs;
        float gc = g2[co];
        g_A2[co] = rs * gc;
        g_B2[co] = b2[co] - mus * rs * gc;
    }
}

// ---------------- final BN2 normalize (in-place on d_out, one FMA) ----------------
__global__ void k_norm(float* __restrict__ out) {
    int i = blockIdx.x*blockDim.x + threadIdx.x;
    if (i >= TOT2) return;
    int c = (i / HW2) & (C2 - 1);
    out[i] = fmaf(out[i], g_A2[c], g_B2[c]);
}

// ---------------- launch ----------------
extern "C" void kernel_launch(void* const* d_in, const int* in_sizes, int n_in,
                              void* d_out, int out_size) {
    const float* x  = (const float*)d_in[0];
    const float* w1 = (const float*)d_in[1];
    const float* g1 = (const float*)d_in[2];
    const float* b1 = (const float*)d_in[3];
    const float* w2 = (const float*)d_in[4];
    const float* g2 = (const float*)d_in[5];
    const float* b2 = (const float*)d_in[6];
    const float* ws = (const float*)d_in[7];
    float* out = (float*)d_out;

    k_abs_partial<<<dim3(128, 3), 256>>>(w1, w2, ws);
    k_abs_final<<<1, 128>>>();
    k_pack_w<<<112, 256>>>(w1, w2, ws);
    k_pack_x<<<(NN*HW1/4 + 255)/256, 256>>>(x);
    k_conv1<<<dim3(H2, NN), 224>>>();
    k_stats1<<<C2, 512>>>(g1, b1);
    k_pack_o1<<<dim3(25, NN), 256>>>();
    k_conv2<<<dim3(H2, NN, 2), 224>>>(out);
    k_stats2<<<C2, 512>>>(out, g2, b2);
    k_norm<<<(TOT2 + 255)/256, 256>>>(out);
}

// round 6
// speedup vs baseline: 1.4379x; 1.0119x over previous
#include <cuda_runtime.h>
#include <cstdint>

#define NN 64
#define C1 128
#define C2 256
#define H1 56
#define W1 56
#define H2 28
#define W2 28
#define HW1 (H1*W1)        // 3136
#define HW2 (H2*W2)        // 784
#define NPIX (NN*HW2)      // 50176
#define TOT2 (NN*C2*HW2)   // 12845056

// ---------------- scratch (static device globals; no runtime allocation) ----------------
__device__ uint4 g_xb[NN*H1*W1];     // packed sign(x): [n][h][w], 128 ch -> 4 words
__device__ uint4 g_w1b[C2*9];        // packed sign(w1): [co][tap], 128 ch -> 4 words
__device__ uint4 g_w2b[C2*9*2];      // packed sign(w2): [co][tap][2], 256 ch -> 8 words
__device__ uint4 g_wsb[C2];          // packed sign(ws): [co], 128 ch -> 4 words
__device__ uint4 g_o1b[NPIX*2];      // packed sign(BN1 out): [n][oh][ow][2]
__device__ short g_t1[TOT2];         // conv1 integer dot (pre-scale, pre-BN1)
__device__ float g_part[3*128];      // partial |w| sums (t*128 + blk)
__device__ float g_A1[C2], g_B1[C2]; // BN1 binarize affine: sign(A1*I + B1)
__device__ float g_A2[C2], g_B2[C2]; // BN2 normalize affine: v*A2 + B2

// ---------------- |w| partial sums (stage 1 of alpha; finalize folded downstream) ----------------
__global__ void k_abs_partial(const float* __restrict__ w1, const float* __restrict__ w2,
                              const float* __restrict__ ws) {
    int t = blockIdx.y;
    const float* s = (t == 0) ? w1 : ((t == 1) ? w2 : ws);
    int n = (t == 0) ? C2*C1*9 : ((t == 1) ? C2*C2*9 : C2*C1);
    float acc = 0.f;
    for (int i = blockIdx.x*blockDim.x + threadIdx.x; i < n; i += gridDim.x*blockDim.x)
        acc += fabsf(s[i]);
    __shared__ float sh[256];
    sh[threadIdx.x] = acc; __syncthreads();
    for (int o = 128; o > 0; o >>= 1) {
        if (threadIdx.x < o) sh[threadIdx.x] += sh[threadIdx.x + o];
        __syncthreads();
    }
    if (threadIdx.x == 0) g_part[t*128 + blockIdx.x] = sh[0];
}

// ---------------- pack weight sign bits ----------------
__global__ void k_pack_w(const float* __restrict__ w1, const float* __restrict__ w2,
                         const float* __restrict__ ws) {
    int idx = blockIdx.x*blockDim.x + threadIdx.x;
    if (idx < C2*9*4) {
        int co = idx/36, rem = idx%36, tap = rem/4, wd = rem%4;
        unsigned b = 0;
        for (int j = 0; j < 32; j++) {
            float v = w1[(co*C1 + wd*32 + j)*9 + tap];
            b |= (v >= 0.f ? 1u : 0u) << j;
        }
        ((unsigned*)g_w1b)[(co*9 + tap)*4 + wd] = b;
    } else if (idx < C2*9*4 + C2*9*8) {
        int k = idx - C2*9*4;
        int co = k/72, rem = k%72, tap = rem/8, wd = rem%8;
        unsigned b = 0;
        for (int j = 0; j < 32; j++) {
            float v = w2[(co*C2 + wd*32 + j)*9 + tap];
            b |= (v >= 0.f ? 1u : 0u) << j;
        }
        ((unsigned*)g_w2b)[(co*9 + tap)*8 + wd] = b;
    } else if (idx < C2*9*4 + C2*9*8 + C2*4) {
        int k = idx - (C2*9*4 + C2*9*8);
        int co = k/4, wd = k%4;
        unsigned b = 0;
        for (int j = 0; j < 32; j++) {
            float v = ws[co*C1 + wd*32 + j];
            b |= (v >= 0.f ? 1u : 0u) << j;
        }
        ((unsigned*)g_wsb)[co*4 + wd] = b;
    }
}

// ---------------- pack sign(x) along channels (R2 scalar form: 784 blocks, high MLP) ----------------
__global__ void k_pack_x(const float* __restrict__ x) {
    int p = blockIdx.x*blockDim.x + threadIdx.x;
    if (p >= NN*HW1) return;
    int n = p / HW1, hw = p - n*HW1;
    const unsigned* xu = (const unsigned*)x;
    unsigned wd[4];
    #pragma unroll
    for (int q = 0; q < 4; q++) {
        unsigned b = 0;
        #pragma unroll 8
        for (int j = 0; j < 32; j++) {
            unsigned u = xu[(n*C1 + q*32 + j)*HW1 + hw];
            b |= ((~u) >> 31) << j;    // 1 iff sign bit clear (v >= 0)
        }
        wd[q] = b;
    }
    g_xb[p] = make_uint4(wd[0], wd[1], wd[2], wd[3]);
}

// ---------------- conv1: 3x3 s2 p1; 2 output rows per block, weights staged once ----------------
__global__ void __launch_bounds__(224, 2) k_conv1() {
    int oh0 = blockIdx.x * 2, n = blockIdx.y;
    __shared__ uint4 sin_[5*W1];        // rows ih = 2*oh0-1 .. 2*oh0+3   (4480 B)
    __shared__ uint4 sw[C2*9];          // 36864 B
    for (int i = threadIdx.x; i < 5*W1; i += 224) {
        int r = i / W1, c = i - r*W1;
        int ih = 2*oh0 - 1 + r;
        if (ih >= 0) sin_[i] = g_xb[(n*H1 + ih)*W1 + c];
    }
    for (int i = threadIdx.x; i < C2*9; i += 224) sw[i] = g_w1b[i];
    __syncthreads();
    int ow = threadIdx.x % 28;
    int cog = threadIdx.x / 28;
    #pragma unroll
    for (int rr = 0; rr < 2; rr++) {
        int oh = oh0 + rr;
        uint4 xin[9]; unsigned vm[9]; int nval = 0;
        #pragma unroll
        for (int kh = 0; kh < 3; kh++)
            #pragma unroll
            for (int kw = 0; kw < 3; kw++) {
                int t = kh*3 + kw;
                int ih = 2*oh - 1 + kh, iw = 2*ow - 1 + kw;
                bool v = (ih >= 0) && (iw >= 0);
                vm[t] = v ? 0xFFFFFFFFu : 0u; nval += v ? 1 : 0;
                int iwc = iw < 0 ? 0 : iw;
                xin[t] = sin_[(2*rr + kh)*W1 + iwc];
            }
        int base = 128 * nval;
        int obase = ((n*C2)*H2 + oh)*W2 + ow;
        for (int i = 0; i < 32; i++) {
            int co = cog*32 + i;
            const uint4* wp = &sw[co*9];
            int p0 = 0, p1 = 0, p2 = 0, p3 = 0;
            #pragma unroll
            for (int t = 0; t < 9; t++) {
                uint4 w = wp[t]; unsigned m = vm[t];
                p0 += __popc((xin[t].x ^ w.x) & m);
                p1 += __popc((xin[t].y ^ w.y) & m);
                p2 += __popc((xin[t].z ^ w.z) & m);
                p3 += __popc((xin[t].w ^ w.w) & m);
            }
            int pop = (p0 + p1) + (p2 + p3);
            g_t1[obase + co*HW2] = (short)(base - 2*pop);
        }
    }
}

// ---------------- BN1 stats (exact int accumulation) + alpha1 finalize ----------------
__global__ void __launch_bounds__(512) k_stats1(const float* __restrict__ g1,
                                                const float* __restrict__ b1) {
    __shared__ float s_a1;
    int tid = threadIdx.x;
    if (tid < 32) {    // warp 0: reduce alpha1 partials
        float v = g_part[tid] + g_part[tid+32] + g_part[tid+64] + g_part[tid+96];
        #pragma unroll
        for (int o = 16; o > 0; o >>= 1) v += __shfl_xor_sync(0xFFFFFFFFu, v, o);
        if (tid == 0) s_a1 = v / (float)(C2*C1*9);
    }
    int co = blockIdx.x;
    int s = 0; long long s2 = 0;
    for (int j = tid; j < NPIX/2; j += 512) {
        int i = 2*j;
        int n = i / HW2, r = i - n*HW2;
        unsigned u = *(const unsigned*)&g_t1[(n*C2 + co)*HW2 + r];
        int v0 = (int)(short)(u & 0xFFFFu);
        int v1 = (int)(short)(u >> 16);
        s += v0 + v1;
        s2 += (long long)(v0*v0 + v1*v1);
    }
    __shared__ int sa[512]; __shared__ long long sb[512];
    sa[tid] = s; sb[tid] = s2; __syncthreads();
    for (int o = 256; o > 0; o >>= 1) {
        if (tid < o) { sa[tid] += sa[tid+o]; sb[tid] += sb[tid+o]; }
        __syncthreads();
    }
    if (tid == 0) {
        double a1 = (double)s_a1;
        double mi  = (double)sa[0] / (double)NPIX;
        double vi  = (double)sb[0] / (double)NPIX - mi*mi;
        double mu  = a1 * mi;
        double var = a1*a1 * vi;
        float rs = (float)(1.0 / sqrt(var + 1e-5));
        float mus = (float)mu;
        float gc = g1[co];
        g_A1[co] = (float)a1 * rs * gc;
        g_B1[co] = b1[co] - mus * rs * gc;
    }
}

// ---------------- binarize+pack BN1 output: smem transpose + ballot ----------------
__global__ void __launch_bounds__(256) k_pack_o1() {
    __shared__ int   sarr[C2*33];
    __shared__ float shA[C2], shB[C2];
    int tid = threadIdx.x, wq = tid >> 5, lane = tid & 31;
    int tidx = blockIdx.x, n = blockIdx.y;
    int hw0 = tidx * 32;
    int P = (hw0 + 32 <= HW2) ? 32 : (HW2 - hw0);
    if (tid < C2) { shA[tid] = g_A1[tid]; shB[tid] = g_B1[tid]; }
    for (int c = wq; c < C2; c += 8) {
        if (lane < P)
            sarr[c*33 + lane] = (int)g_t1[(n*C2 + c)*HW2 + hw0 + lane];
    }
    __syncthreads();
    int ch = wq*32 + lane;
    float A = shA[ch], B = shB[ch];
    unsigned myword = 0;
    for (int px = 0; px < P; px++) {
        float o = fmaf(A, (float)sarr[ch*33 + px], B);
        unsigned w = __ballot_sync(0xFFFFFFFFu, o >= 0.f);
        if (lane == px) myword = w;
    }
    if (lane < P)
        ((unsigned*)g_o1b)[(n*HW2 + hw0 + lane)*8 + wq] = myword;
}

// ---------------- conv2 (3x3 s1 p1) + 1x1 shortcut; 2 rows/block, co split over z ----------------
__global__ void __launch_bounds__(224, 2) k_conv2(float* __restrict__ out) {
    int oh0 = blockIdx.x * 2, n = blockIdx.y, coh = blockIdx.z;
    __shared__ uint4 sin_[4*W2*2];      // rows ih = oh0-1 .. oh0+2   (3584 B)
    __shared__ uint4 sw[128*18];        // 36864 B
    __shared__ uint4 sws[128];          // 2048 B
    __shared__ float s_a2, s_as;
    int tid = threadIdx.x;
    for (int i = tid; i < 4*W2*2; i += 224) {
        int r = i / (W2*2); int rem = i - r*(W2*2);
        int ih = oh0 - 1 + r;
        if (ih >= 0 && ih < H2) sin_[i] = g_o1b[((n*H2 + ih)*W2)*2 + rem];
    }
    for (int i = tid; i < 128*18; i += 224) sw[i] = g_w2b[coh*128*18 + i];
    if (tid < 128) sws[tid] = g_wsb[coh*128 + tid];
    if (tid < 32) {     // warp 0: finalize alpha2 / alpha_s from partials
        float v2 = g_part[128+tid] + g_part[160+tid] + g_part[192+tid] + g_part[224+tid];
        float vs = g_part[256+tid] + g_part[288+tid] + g_part[320+tid] + g_part[352+tid];
        #pragma unroll
        for (int o = 16; o > 0; o >>= 1) {
            v2 += __shfl_xor_sync(0xFFFFFFFFu, v2, o);
            vs += __shfl_xor_sync(0xFFFFFFFFu, vs, o);
        }
        if (tid == 0) { s_a2 = v2 / (float)(C2*C2*9); s_as = vs / (float)(C2*C1); }
    }
    __syncthreads();
    int ow = tid % 28, cog = tid / 28;
    float a2 = s_a2, as_ = s_as;
    #pragma unroll
    for (int rr = 0; rr < 2; rr++) {
        int oh = oh0 + rr;
        uint4 xa[9], xb2[9]; unsigned vm[9]; int nval = 0;
        #pragma unroll
        for (int kh = 0; kh < 3; kh++)
            #pragma unroll
            for (int kw = 0; kw < 3; kw++) {
                int t = kh*3 + kw;
                int ih = oh - 1 + kh, iw = ow - 1 + kw;
                bool v = ((unsigned)ih < H2) && ((unsigned)iw < W2);
                vm[t] = v ? 0xFFFFFFFFu : 0u; nval += v ? 1 : 0;
                int iwc = iw < 0 ? 0 : (iw > W2-1 ? W2-1 : iw);
                xa[t]  = sin_[((rr + kh)*W2 + iwc)*2];
                xb2[t] = sin_[((rr + kh)*W2 + iwc)*2 + 1];
            }
        uint4 xs = g_xb[(n*H1 + 2*oh)*W1 + 2*ow];
        float base = 256.f * (float)nval;
        int obase = ((n*C2 + coh*128)*H2 + oh)*W2 + ow;
        for (int i = 0; i < 16; i++) {
            int col = cog*16 + i;
            const uint4* wp = &sw[col*18];
            int p0 = 0, p1 = 0, p2 = 0, p3 = 0;
            #pragma unroll
            for (int t = 0; t < 9; t++) {
                uint4 wa = wp[2*t], wb = wp[2*t + 1]; unsigned m = vm[t];
                p0 += __popc((xa[t].x ^ wa.x) & m) + __popc((xb2[t].x ^ wb.x) & m);
                p1 += __popc((xa[t].y ^ wa.y) & m) + __popc((xb2[t].y ^ wb.y) & m);
                p2 += __popc((xa[t].z ^ wa.z) & m) + __popc((xb2[t].z ^ wb.z) & m);
                p3 += __popc((xa[t].w ^ wa.w) & m) + __popc((xb2[t].w ^ wb.w) & m);
            }
            int pop = (p0 + p1) + (p2 + p3);
            uint4 wv = sws[col];
            int ps = __popc(xs.x ^ wv.x) + __popc(xs.y ^ wv.y)
                   + __popc(xs.z ^ wv.z) + __popc(xs.w ^ wv.w);
            out[obase + col*HW2] = fmaf(a2, base - 2.f*(float)pop, as_ * (128.f - 2.f*(float)ps));
        }
    }
}

// ---------------- BN2 stats: f32 per-thread, double block tree ----------------
__global__ void __launch_bounds__(512) k_stats2(const float* __restrict__ out,
                                                const float* __restrict__ g2,
                                                const float* __restrict__ b2) {
    int co = blockIdx.x;
    float s = 0.f, s2 = 0.f;
    for (int i = threadIdx.x; i < NPIX; i += 512) {
        int n = i / HW2, r = i - n*HW2;
        float v = out[(n*C2 + co)*HW2 + r];
        s += v; s2 = fmaf(v, v, s2);
    }
    __shared__ double sa[512], sb[512];
    sa[threadIdx.x] = (double)s; sb[threadIdx.x] = (double)s2; __syncthreads();
    for (int o = 256; o > 0; o >>= 1) {
        if (threadIdx.x < o) { sa[threadIdx.x] += sa[threadIdx.x+o]; sb[threadIdx.x] += sb[threadIdx.x+o]; }
        __syncthreads();
    }
    if (threadIdx.x == 0) {
        double m = sa[0] / (double)NPIX;
        double var = sb[0] / (double)NPIX - m*m;
        float rs = (float)(1.0 / sqrt(var + 1e-5));
        float mus = (float)m;
        float gc = g2[co];
        g_A2[co] = rs * gc;
        g_B2[co] = b2[co] - mus * rs * gc;
    }
}

// ---------------- final BN2 normalize (in-place on d_out, one FMA) ----------------
__global__ void k_norm(float* __restrict__ out) {
    int i = blockIdx.x*blockDim.x + threadIdx.x;
    if (i >= TOT2) return;
    int c = (i / HW2) & (C2 - 1);
    out[i] = fmaf(out[i], g_A2[c], g_B2[c]);
}

// ---------------- launch ----------------
extern "C" void kernel_launch(void* const* d_in, const int* in_sizes, int n_in,
                              void* d_out, int out_size) {
    const float* x  = (const float*)d_in[0];
    const float* w1 = (const float*)d_in[1];
    const float* g1 = (const float*)d_in[2];
    const float* b1 = (const float*)d_in[3];
    const float* w2 = (const float*)d_in[4];
    const float* g2 = (const float*)d_in[5];
    const float* b2 = (const float*)d_in[6];
    const float* ws = (const float*)d_in[7];
    float* out = (float*)d_out;

    k_abs_partial<<<dim3(128, 3), 256>>>(w1, w2, ws);
    k_pack_w<<<112, 256>>>(w1, w2, ws);
    k_pack_x<<<(NN*HW1 + 255)/256, 256>>>(x);
    k_conv1<<<dim3(14, NN), 224>>>();
    k_stats1<<<C2, 512>>>(g1, b1);
    k_pack_o1<<<dim3(25, NN), 256>>>();
    k_conv2<<<dim3(14, NN, 2), 224>>>(out);
    k_stats2<<<C2, 512>>>(out, g2, b2);
    k_norm<<<(TOT2 + 255)/256, 256>>>(out);
}